// round 16
// baseline (speedup 1.0000x reference)
#include <cuda_runtime.h>
#include <math.h>

#define L_SEQ 4096
#define B_SZ  64
#define C_IN  256
#define H_SZ  256
#define WSM_PAD 132  // smem row stride (floats) for the k=128..255 half: 528B, 16B-aligned, conflict-free

// ---- packed fp32x2 helpers (phase 1 only; each lane is IEEE rn fp32 fma) ----
__device__ __forceinline__ unsigned long long fma2(unsigned long long a,
                                                   unsigned long long b,
                                                   unsigned long long c) {
    unsigned long long d;
    asm("fma.rn.f32x2 %0, %1, %2, %3;" : "=l"(d) : "l"(a), "l"(b), "l"(c));
    return d;
}
__device__ __forceinline__ unsigned long long dup2(float a) {
    unsigned long long d;
    asm("mov.b64 %0, {%1, %1};" : "=l"(d) : "f"(a));
    return d;
}
__device__ __forceinline__ void unpack2(unsigned long long v, float& lo, float& hi) {
    asm("mov.b64 {%0, %1}, %2;" : "=f"(lo), "=f"(hi) : "l"(v));
}

// ---- XLA:CPU EmitFastTanh, with_fma=true (validated bit-exact in R15) ----
__device__ __forceinline__ float xla_tanh(float x) {
    const float kClamp = 7.99881172180175781f;
    float xc = fminf(fmaxf(x, -kClamp), kClamp);
    float x2 = __fmul_rn(xc, xc);
    float p  = __fmaf_rn(x2, -2.76076847742355e-16f, 2.00018790482477e-13f);
    p = __fmaf_rn(x2, p, -8.60467152213735e-11f);
    p = __fmaf_rn(x2, p,  5.12229709037114e-08f);
    p = __fmaf_rn(x2, p,  1.48572235717979e-05f);
    p = __fmaf_rn(x2, p,  6.37261928875436e-04f);
    p = __fmaf_rn(x2, p,  4.89352455891786e-03f);
    p = __fmul_rn(xc, p);
    float q  = __fmaf_rn(x2, 1.19825839466702e-06f, 1.18534705686654e-04f);
    q = __fmaf_rn(x2, q, 2.26843463243900e-03f);
    q = __fmaf_rn(x2, q, 4.89352518554385e-03f);
    float r = __fdiv_rn(p, q);
    return (fabsf(x) < 0.0004f) ? x : r;
}

// ---------------------------------------------------------------------------
// Phase 1 (unchanged from R15, bit-exact): out[m,n] = sum_k X[m,k]*W_ih[n,k] + b[n]
// ---------------------------------------------------------------------------
__global__ void __launch_bounds__(256, 2)
rnn_xproj(const float* __restrict__ X, const float* __restrict__ W,
          const float* __restrict__ bias, float* __restrict__ out)
{
    __shared__ __align__(16) float As[16][128];
    __shared__ __align__(16) float Bs[16][128];

    const int t  = threadIdx.x;
    const int m0 = (blockIdx.x >> 1) * 128;
    const int n0 = (blockIdx.x & 1) * 128;
    const int tn = t & 15, tm = t >> 4;

    unsigned long long acc[8][4];
#pragma unroll
    for (int i = 0; i < 8; i++)
#pragma unroll
        for (int j = 0; j < 4; j++) acc[i][j] = 0ULL;

    const float* Xb = X + (long long)m0 * C_IN;
    const float* Wb = W + (long long)n0 * C_IN;

    for (int ic = 0; ic < 16; ic++) {
        const int kc = ic * 16;
        __syncthreads();
#pragma unroll
        for (int q = 0; q < 2; q++) {
            int f = t + q * 256;
            int row = f >> 2, c4 = f & 3;
            float4 xv = *reinterpret_cast<const float4*>(Xb + row * C_IN + kc + c4 * 4);
            float4 wv = *reinterpret_cast<const float4*>(Wb + row * C_IN + kc + c4 * 4);
            As[c4 * 4 + 0][row] = xv.x; As[c4 * 4 + 1][row] = xv.y;
            As[c4 * 4 + 2][row] = xv.z; As[c4 * 4 + 3][row] = xv.w;
            Bs[c4 * 4 + 0][row] = wv.x; Bs[c4 * 4 + 1][row] = wv.y;
            Bs[c4 * 4 + 2][row] = wv.z; Bs[c4 * 4 + 3][row] = wv.w;
        }
        __syncthreads();
#pragma unroll
        for (int kk = 0; kk < 16; kk++) {
            float4 aA = *reinterpret_cast<const float4*>(&As[kk][tm * 8]);
            float4 aB = *reinterpret_cast<const float4*>(&As[kk][tm * 8 + 4]);
            ulonglong2 b01 = *reinterpret_cast<const ulonglong2*>(&Bs[kk][tn * 8]);
            ulonglong2 b23 = *reinterpret_cast<const ulonglong2*>(&Bs[kk][tn * 8 + 4]);
            unsigned long long ad[8];
            ad[0] = dup2(aA.x); ad[1] = dup2(aA.y); ad[2] = dup2(aA.z); ad[3] = dup2(aA.w);
            ad[4] = dup2(aB.x); ad[5] = dup2(aB.y); ad[6] = dup2(aB.z); ad[7] = dup2(aB.w);
#pragma unroll
            for (int mi = 0; mi < 8; mi++) {
                acc[mi][0] = fma2(ad[mi], b01.x, acc[mi][0]);
                acc[mi][1] = fma2(ad[mi], b01.y, acc[mi][1]);
                acc[mi][2] = fma2(ad[mi], b23.x, acc[mi][2]);
                acc[mi][3] = fma2(ad[mi], b23.y, acc[mi][3]);
            }
        }
    }

    float4 bv0 = *reinterpret_cast<const float4*>(bias + n0 + tn * 8);
    float4 bv1 = *reinterpret_cast<const float4*>(bias + n0 + tn * 8 + 4);
#pragma unroll
    for (int mi = 0; mi < 8; mi++) {
        long long m = m0 + tm * 8 + mi;
        float4 o0, o1;
        unpack2(acc[mi][0], o0.x, o0.y);
        unpack2(acc[mi][1], o0.z, o0.w);
        unpack2(acc[mi][2], o1.x, o1.y);
        unpack2(acc[mi][3], o1.z, o1.w);
        o0.x = __fadd_rn(o0.x, bv0.x); o0.y = __fadd_rn(o0.y, bv0.y);
        o0.z = __fadd_rn(o0.z, bv0.z); o0.w = __fadd_rn(o0.w, bv0.w);
        o1.x = __fadd_rn(o1.x, bv1.x); o1.y = __fadd_rn(o1.y, bv1.y);
        o1.z = __fadd_rn(o1.z, bv1.z); o1.w = __fadd_rn(o1.w, bv1.w);
        *reinterpret_cast<float4*>(out + m * H_SZ + n0 + tn * 8)     = o0;
        *reinterpret_cast<float4*>(out + m * H_SZ + n0 + tn * 8 + 4) = o1;
    }
}

// ---------------------------------------------------------------------------
// Phase 2: one CTA (256 threads) per batch element; thread j owns output row j.
// W row k=0..127 in registers (32 x float4), k=128..255 in padded smem.
// h exchange = STS + __syncthreads (double-buffered). Arithmetic identical to
// R15 (single acc, strictly ascending k, __fadd_rn, xla_tanh) -> stays bit-exact.
// ---------------------------------------------------------------------------
__global__ void __launch_bounds__(256, 1)
rnn_recur(float* out, const float* __restrict__ h0, const float* __restrict__ W_hh)
{
    extern __shared__ __align__(16) float sm[];
    float* Wsm = sm;                         // [256][WSM_PAD]
    float* hb[2] = { sm + 256 * WSM_PAD, sm + 256 * WSM_PAD + H_SZ };

    const int j = threadIdx.x;               // 0..255: output row
    const int b = blockIdx.x;                // batch element

    // Load W_hh row j: first half to registers, second half to padded smem.
    float4 wreg[32];
    {
        const float4* wr = reinterpret_cast<const float4*>(W_hh + j * H_SZ);
#pragma unroll
        for (int k = 0; k < 32; k++) wreg[k] = wr[k];
        float4* ws = reinterpret_cast<float4*>(Wsm + j * WSM_PAD);
#pragma unroll
        for (int k = 0; k < 32; k++) ws[k] = wr[32 + k];
    }
    hb[0][j] = h0[b * H_SZ + j];
    __syncthreads();

    const float4* wsm4 = reinterpret_cast<const float4*>(Wsm + j * WSM_PAD);
    float xw_next = out[(0 * B_SZ + b) * H_SZ + j];

    for (int l = 0; l < L_SEQ; l++) {
        const int cur = l & 1;
        float xw = xw_next;
        if (l + 1 < L_SEQ)
            xw_next = out[((l + 1) * B_SZ + b) * H_SZ + j];

        // dot = sum_{k=0..255 ascending} fma(W[j,k], h[k], acc), acc0 = 0.0f
        const float4* hr = reinterpret_cast<const float4*>(hb[cur]);
        float acc = 0.0f;
#pragma unroll
        for (int k = 0; k < 32; k++) {          // k = 0..127 from registers
            float4 hv = hr[k];
            acc = __fmaf_rn(wreg[k].x, hv.x, acc);
            acc = __fmaf_rn(wreg[k].y, hv.y, acc);
            acc = __fmaf_rn(wreg[k].z, hv.z, acc);
            acc = __fmaf_rn(wreg[k].w, hv.w, acc);
        }
#pragma unroll
        for (int k = 0; k < 32; k++) {          // k = 128..255 from smem
            float4 wv = wsm4[k];
            float4 hv = hr[32 + k];
            acc = __fmaf_rn(wv.x, hv.x, acc);
            acc = __fmaf_rn(wv.y, hv.y, acc);
            acc = __fmaf_rn(wv.z, hv.z, acc);
            acc = __fmaf_rn(wv.w, hv.w, acc);
        }

        float z = __fadd_rn(xw, acc);
        float h = xla_tanh(z);
        out[((long long)l * B_SZ + b) * H_SZ + j] = h;     // outputs[l]

        if (l + 1 < L_SEQ) {
            hb[cur ^ 1][j] = h;                            // publish new h
            __syncthreads();                               // one barrier per step
        } else {
            out[(long long)L_SEQ * B_SZ * H_SZ + b * H_SZ + j] = h;  // h_last
        }
    }
}

extern "C" void kernel_launch(void* const* d_in, const int* in_sizes, int n_in,
                              void* d_out, int out_size) {
    const float* x    = (const float*)d_in[0];
    const float* h0   = (const float*)d_in[1];
    const float* W_ih = (const float*)d_in[2];
    const float* W_hh = (const float*)d_in[3];
    const float* bias = (const float*)d_in[4];
    float* out = (float*)d_out;

    static int smem_set = 0;
    const int dyn_smem = (256 * WSM_PAD + 2 * H_SZ) * sizeof(float);  // 137216 B
    if (!smem_set) {
        cudaFuncSetAttribute(rnn_recur, cudaFuncAttributeMaxDynamicSharedMemorySize, dyn_smem);
        smem_set = 1;
    }

    // Phase 1: xW + b into the outputs region of d_out.
    rnn_xproj<<<(L_SEQ * B_SZ / 128) * 2, 256>>>(x, W_ih, bias, out);
    // Phase 2: sequential recurrence (bit-exact order), in-place over outputs.
    rnn_recur<<<B_SZ, 256, dyn_smem>>>(out, h0, W_hh);
}

// round 17
// speedup vs baseline: 1.6080x; 1.6080x over previous
#include <cuda_runtime.h>
#include <math.h>

#define L_SEQ 4096
#define B_SZ  64
#define C_IN  256
#define H_SZ  256

#define W_REG4   40   // float4's of W per thread in registers (k = 0..159)
#define W_SMEM4  24   // float4's of W per thread in smem      (k = 160..255)

// ---- packed fp32x2 helpers (phase 1 only; each lane is IEEE rn fp32 fma) ----
__device__ __forceinline__ unsigned long long fma2(unsigned long long a,
                                                   unsigned long long b,
                                                   unsigned long long c) {
    unsigned long long d;
    asm("fma.rn.f32x2 %0, %1, %2, %3;" : "=l"(d) : "l"(a), "l"(b), "l"(c));
    return d;
}
__device__ __forceinline__ unsigned long long dup2(float a) {
    unsigned long long d;
    asm("mov.b64 %0, {%1, %1};" : "=l"(d) : "f"(a));
    return d;
}
__device__ __forceinline__ void unpack2(unsigned long long v, float& lo, float& hi) {
    asm("mov.b64 {%0, %1}, %2;" : "=f"(lo), "=f"(hi) : "l"(v));
}

// ---- XLA:CPU EmitFastTanh, with_fma=true (validated bit-exact in R15/R16) ----
__device__ __forceinline__ float xla_tanh(float x) {
    const float kClamp = 7.99881172180175781f;
    float xc = fminf(fmaxf(x, -kClamp), kClamp);
    float x2 = __fmul_rn(xc, xc);
    float p  = __fmaf_rn(x2, -2.76076847742355e-16f, 2.00018790482477e-13f);
    p = __fmaf_rn(x2, p, -8.60467152213735e-11f);
    p = __fmaf_rn(x2, p,  5.12229709037114e-08f);
    p = __fmaf_rn(x2, p,  1.48572235717979e-05f);
    p = __fmaf_rn(x2, p,  6.37261928875436e-04f);
    p = __fmaf_rn(x2, p,  4.89352455891786e-03f);
    p = __fmul_rn(xc, p);
    float q  = __fmaf_rn(x2, 1.19825839466702e-06f, 1.18534705686654e-04f);
    q = __fmaf_rn(x2, q, 2.26843463243900e-03f);
    q = __fmaf_rn(x2, q, 4.89352518554385e-03f);
    float r = __fdiv_rn(p, q);
    return (fabsf(x) < 0.0004f) ? x : r;
}

// ---------------------------------------------------------------------------
// Phase 1 (unchanged, bit-exact): out[m,n] = sum_k X[m,k]*W_ih[n,k] + b[n]
// ---------------------------------------------------------------------------
__global__ void __launch_bounds__(256, 2)
rnn_xproj(const float* __restrict__ X, const float* __restrict__ W,
          const float* __restrict__ bias, float* __restrict__ out)
{
    __shared__ __align__(16) float As[16][128];
    __shared__ __align__(16) float Bs[16][128];

    const int t  = threadIdx.x;
    const int m0 = (blockIdx.x >> 1) * 128;
    const int n0 = (blockIdx.x & 1) * 128;
    const int tn = t & 15, tm = t >> 4;

    unsigned long long acc[8][4];
#pragma unroll
    for (int i = 0; i < 8; i++)
#pragma unroll
        for (int j = 0; j < 4; j++) acc[i][j] = 0ULL;

    const float* Xb = X + (long long)m0 * C_IN;
    const float* Wb = W + (long long)n0 * C_IN;

    for (int ic = 0; ic < 16; ic++) {
        const int kc = ic * 16;
        __syncthreads();
#pragma unroll
        for (int q = 0; q < 2; q++) {
            int f = t + q * 256;
            int row = f >> 2, c4 = f & 3;
            float4 xv = *reinterpret_cast<const float4*>(Xb + row * C_IN + kc + c4 * 4);
            float4 wv = *reinterpret_cast<const float4*>(Wb + row * C_IN + kc + c4 * 4);
            As[c4 * 4 + 0][row] = xv.x; As[c4 * 4 + 1][row] = xv.y;
            As[c4 * 4 + 2][row] = xv.z; As[c4 * 4 + 3][row] = xv.w;
            Bs[c4 * 4 + 0][row] = wv.x; Bs[c4 * 4 + 1][row] = wv.y;
            Bs[c4 * 4 + 2][row] = wv.z; Bs[c4 * 4 + 3][row] = wv.w;
        }
        __syncthreads();
#pragma unroll
        for (int kk = 0; kk < 16; kk++) {
            float4 aA = *reinterpret_cast<const float4*>(&As[kk][tm * 8]);
            float4 aB = *reinterpret_cast<const float4*>(&As[kk][tm * 8 + 4]);
            ulonglong2 b01 = *reinterpret_cast<const ulonglong2*>(&Bs[kk][tn * 8]);
            ulonglong2 b23 = *reinterpret_cast<const ulonglong2*>(&Bs[kk][tn * 8 + 4]);
            unsigned long long ad[8];
            ad[0] = dup2(aA.x); ad[1] = dup2(aA.y); ad[2] = dup2(aA.z); ad[3] = dup2(aA.w);
            ad[4] = dup2(aB.x); ad[5] = dup2(aB.y); ad[6] = dup2(aB.z); ad[7] = dup2(aB.w);
#pragma unroll
            for (int mi = 0; mi < 8; mi++) {
                acc[mi][0] = fma2(ad[mi], b01.x, acc[mi][0]);
                acc[mi][1] = fma2(ad[mi], b01.y, acc[mi][1]);
                acc[mi][2] = fma2(ad[mi], b23.x, acc[mi][2]);
                acc[mi][3] = fma2(ad[mi], b23.y, acc[mi][3]);
            }
        }
    }

    float4 bv0 = *reinterpret_cast<const float4*>(bias + n0 + tn * 8);
    float4 bv1 = *reinterpret_cast<const float4*>(bias + n0 + tn * 8 + 4);
#pragma unroll
    for (int mi = 0; mi < 8; mi++) {
        long long m = m0 + tm * 8 + mi;
        float4 o0, o1;
        unpack2(acc[mi][0], o0.x, o0.y);
        unpack2(acc[mi][1], o0.z, o0.w);
        unpack2(acc[mi][2], o1.x, o1.y);
        unpack2(acc[mi][3], o1.z, o1.w);
        o0.x = __fadd_rn(o0.x, bv0.x); o0.y = __fadd_rn(o0.y, bv0.y);
        o0.z = __fadd_rn(o0.z, bv0.z); o0.w = __fadd_rn(o0.w, bv0.w);
        o1.x = __fadd_rn(o1.x, bv1.x); o1.y = __fadd_rn(o1.y, bv1.y);
        o1.z = __fadd_rn(o1.z, bv1.z); o1.w = __fadd_rn(o1.w, bv1.w);
        *reinterpret_cast<float4*>(out + m * H_SZ + n0 + tn * 8)     = o0;
        *reinterpret_cast<float4*>(out + m * H_SZ + n0 + tn * 8 + 4) = o1;
    }
}

// ---------------------------------------------------------------------------
// Phase 2: one CTA (256 threads) per batch element; thread j owns output row j.
// W row: k=0..159 in registers (40 x float4); k=160..255 in smem with K-MAJOR
// layout Wsm[k4][j] -> warp lanes read 32 contiguous float4s -> conflict-free
// (fixes the 4-way bank conflict that bound R15/R16).
// Arithmetic identical (single acc, ascending k, __fadd_rn, xla_tanh).
// ---------------------------------------------------------------------------
__global__ void __launch_bounds__(256, 1)
rnn_recur(float* out, const float* __restrict__ h0, const float* __restrict__ W_hh)
{
    extern __shared__ __align__(16) float sm[];
    float4* Wsm4 = reinterpret_cast<float4*>(sm);       // [W_SMEM4][256] float4, k-major
    float*  hb0  = sm + W_SMEM4 * 256 * 4;              // h double buffer
    float*  hb1  = hb0 + H_SZ;

    const int j = threadIdx.x;               // 0..255: output row
    const int b = blockIdx.x;                // batch element

    // Load W_hh row j: k=0..159 to registers, k=160..255 to k-major smem.
    float4 wreg[W_REG4];
    {
        const float4* wr = reinterpret_cast<const float4*>(W_hh + j * H_SZ);
#pragma unroll
        for (int k = 0; k < W_REG4; k++) wreg[k] = wr[k];
#pragma unroll
        for (int k = 0; k < W_SMEM4; k++) Wsm4[k * 256 + j] = wr[W_REG4 + k];
    }
    hb0[j] = h0[b * H_SZ + j];
    __syncthreads();

    float xw_next = out[(0 * B_SZ + b) * H_SZ + j];

    for (int l = 0; l < L_SEQ; l++) {
        float* hcur = (l & 1) ? hb1 : hb0;
        float* hnxt = (l & 1) ? hb0 : hb1;
        float xw = xw_next;
        if (l + 1 < L_SEQ)
            xw_next = out[((l + 1) * B_SZ + b) * H_SZ + j];

        // dot = sum_{k=0..255 ascending} fma(W[j,k], h[k], acc), acc0 = 0.0f
        const float4* hr = reinterpret_cast<const float4*>(hcur);
        float acc = 0.0f;
#pragma unroll
        for (int k = 0; k < W_REG4; k++) {         // k = 0..159 from registers
            float4 hv = hr[k];
            acc = __fmaf_rn(wreg[k].x, hv.x, acc);
            acc = __fmaf_rn(wreg[k].y, hv.y, acc);
            acc = __fmaf_rn(wreg[k].z, hv.z, acc);
            acc = __fmaf_rn(wreg[k].w, hv.w, acc);
        }
#pragma unroll
        for (int k = 0; k < W_SMEM4; k++) {        // k = 160..255 from smem (conflict-free)
            float4 wv = Wsm4[k * 256 + j];
            float4 hv = hr[W_REG4 + k];
            acc = __fmaf_rn(wv.x, hv.x, acc);
            acc = __fmaf_rn(wv.y, hv.y, acc);
            acc = __fmaf_rn(wv.z, hv.z, acc);
            acc = __fmaf_rn(wv.w, hv.w, acc);
        }

        float z = __fadd_rn(xw, acc);
        float h = xla_tanh(z);
        out[((long long)l * B_SZ + b) * H_SZ + j] = h;     // outputs[l]

        if (l + 1 < L_SEQ) {
            hnxt[j] = h;                                   // publish new h
            __syncthreads();                               // one barrier per step
        } else {
            out[(long long)L_SEQ * B_SZ * H_SZ + b * H_SZ + j] = h;  // h_last
        }
    }
}

extern "C" void kernel_launch(void* const* d_in, const int* in_sizes, int n_in,
                              void* d_out, int out_size) {
    const float* x    = (const float*)d_in[0];
    const float* h0   = (const float*)d_in[1];
    const float* W_ih = (const float*)d_in[2];
    const float* W_hh = (const float*)d_in[3];
    const float* bias = (const float*)d_in[4];
    float* out = (float*)d_out;

    static int smem_set = 0;
    const int dyn_smem = (W_SMEM4 * 256 * 4 + 2 * H_SZ) * sizeof(float);  // 100352 B
    if (!smem_set) {
        cudaFuncSetAttribute(rnn_recur, cudaFuncAttributeMaxDynamicSharedMemorySize, dyn_smem);
        smem_set = 1;
    }

    // Phase 1: xW + b into the outputs region of d_out.
    rnn_xproj<<<(L_SEQ * B_SZ / 128) * 2, 256>>>(x, W_ih, bias, out);
    // Phase 2: sequential recurrence (bit-exact order), in-place over outputs.
    rnn_recur<<<B_SZ, 256, dyn_smem>>>(out, h0, W_hh);
}